// round 7
// baseline (speedup 1.0000x reference)
#include <cuda_runtime.h>
#include <math_constants.h>

// Problem constants
#define BN 32
#define TT 1500
#define DD 512
#define KK 2048
#define NQ 8
#define NN (BN * TT)          // 48000 vectors
#define QELEMS (BN * DD * TT) // 24576000 elements of quantized output

// GEMM tiling
#define TM 128
#define TN 128
#define TK 16
#define NITER (DD / TK)       // 32 d-steps per column tile
#define KHALF (KK / 2)        // 1024 codes per half
#define NTILE (NN / TM)       // 375 row tiles
#define AROW (2 * TM)         // duplicated A row width (256 floats)

typedef unsigned long long u64;

// Packed fp32x2 FMA: two IEEE .rn fp32 FMAs per instruction (Blackwell packed
// path; bit-identical to scalar fmaf per lane; ptxas never emits it from C++).
__device__ __forceinline__ u64 ffma2(u64 a, u64 b, u64 c) {
    u64 d;
    asm("fma.rn.f32x2 %0, %1, %2, %3;" : "=l"(d) : "l"(a), "l"(b), "l"(c));
    return d;
}
__device__ __forceinline__ void unpack2(u64 v, float& lo, float& hi) {
    asm("mov.b64 {%0, %1}, %2;" : "=f"(lo), "=f"(hi) : "l"(v));
}

// Scratch (allocation-free rule: __device__ globals)
__device__ __align__(16) float  g_res[QELEMS];   // residual, layout [d][n]  (n = b*TT + t)
__device__ __align__(16) float  g_qo[QELEMS];    // accumulated quantized_out, layout [d][n]
__device__ __align__(16) float  g_x2[NN];        // ||residual_n||^2
__device__ __align__(16) float  g_c2[NQ * KK];   // ||cb_{q,k}||^2
__device__ __align__(16) float  g_bd2[2 * NN];   // per-half best distance
__device__ int    g_bk2[2 * NN];                 // per-half best index
__device__ double g_loss[NQ];                    // per-stage sum of (quant - residual)^2

// ---------------------------------------------------------------------------
// init: transpose x [B,D,T] -> g_res [d][n], zero g_qo and g_loss
// ---------------------------------------------------------------------------
__global__ void k_init(const float* __restrict__ x) {
    int i = blockIdx.x * blockDim.x + threadIdx.x;
    if (i >= QELEMS) return;
    int n = i % NN;
    int d = i / NN;
    int b = n / TT;
    int t = n % TT;
    g_res[i] = x[(size_t)b * (DD * TT) + (size_t)d * TT + t];
    g_qo[i] = 0.0f;
    if (i < NQ) g_loss[i] = 0.0;
}

// ---------------------------------------------------------------------------
// c2[q*KK + k] = sum_d cb[q,k,d]^2   (fp32 mul-then-add, sequential d)
// ---------------------------------------------------------------------------
__global__ void k_c2(const float* __restrict__ cbs) {
    int i = blockIdx.x * blockDim.x + threadIdx.x;
    if (i >= NQ * KK) return;
    const float* row = cbs + (size_t)i * DD;
    float s = 0.0f;
    for (int d = 0; d < DD; d++) {
        float v = __ldg(&row[d]);
        s = __fadd_rn(s, __fmul_rn(v, v));
    }
    g_c2[i] = s;
}

// ---------------------------------------------------------------------------
// x2[n] = sum_d res[d][n]^2  (stage 0; later stages fused into k_update)
// ---------------------------------------------------------------------------
__global__ void k_x2() {
    int n = blockIdx.x * blockDim.x + threadIdx.x;
    if (n >= NN) return;
    float s = 0.0f;
    for (int d = 0; d < DD; d++) {
        float v = g_res[d * NN + n];
        s = __fadd_rn(s, __fmul_rn(v, v));
    }
    g_x2[n] = s;
}

// ---------------------------------------------------------------------------
// Distance GEMM + argmin over one half of the codebook, FFMA2 inner loop.
// blockIdx.x = row tile (0..374), blockIdx.y = code half (0/1).
// A tile stored DUPLICATED in smem ({v,v,w,w}) so the packed {a,a} operand is
// one broadcast LDS.128. B pairs are naturally contiguous.
// dist = fl(fl(x2 - 2*dot) + c2); exact lowest-index tie-break everywhere.
// ---------------------------------------------------------------------------
__global__ __launch_bounds__(256, 2)
void k_argmin(const float* __restrict__ cbq, int q) {
    __shared__ __align__(16) float As[2][TK * AROW];  // 2 x 16KB (duplicated)
    __shared__ __align__(16) float Bs[2][TK * TN];    // 2 x 8KB

    int tid = threadIdx.x;
    int tx = tid & 15;
    int ty = tid >> 4;
    int n0 = blockIdx.x * TM;
    int half = blockIdx.y;
    int kbase = half * KHALF;

    // per-thread load slots (2 float4 for A, 2 for B)
    const int a_dd0  = tid >> 5;            // 0..7
    const int a_dd1  = (tid + 256) >> 5;    // 8..15
    const int a_nn4  = tid & 31;            // float4 slot along n
    const int b_kk0  = tid >> 2;            // 0..63
    const int b_kk1  = (tid + 256) >> 2;    // 64..127
    const int b_dq   = tid & 3;             // float4 slot along d

    float bd[8];
    int   bk[8];
#pragma unroll
    for (int i = 0; i < 8; i++) { bd[i] = CUDART_INF_F; bk[i] = 0x7fffffff; }

    for (int kt = 0; kt < KHALF / TN; kt++) {
        int k0 = kbase + kt * TN;
        u64 acc[8][4];
#pragma unroll
        for (int i = 0; i < 8; i++)
#pragma unroll
            for (int p = 0; p < 4; p++) acc[i][p] = 0ull;

        // ---- fill buffer 0 (d0 = 0) ----
        {
            float4 pa0 = *(const float4*)(&g_res[a_dd0 * NN + n0 + a_nn4 * 4]);
            float4 pa1 = *(const float4*)(&g_res[a_dd1 * NN + n0 + a_nn4 * 4]);
            float4 pb0 = *(const float4*)(&cbq[(size_t)(k0 + b_kk0) * DD + b_dq * 4]);
            float4 pb1 = *(const float4*)(&cbq[(size_t)(k0 + b_kk1) * DD + b_dq * 4]);
            float4* da0 = (float4*)(&As[0][a_dd0 * AROW + a_nn4 * 8]);
            da0[0] = make_float4(pa0.x, pa0.x, pa0.y, pa0.y);
            da0[1] = make_float4(pa0.z, pa0.z, pa0.w, pa0.w);
            float4* da1 = (float4*)(&As[0][a_dd1 * AROW + a_nn4 * 8]);
            da1[0] = make_float4(pa1.x, pa1.x, pa1.y, pa1.y);
            da1[1] = make_float4(pa1.z, pa1.z, pa1.w, pa1.w);
            Bs[0][(b_dq * 4 + 0) * TN + b_kk0] = pb0.x;
            Bs[0][(b_dq * 4 + 1) * TN + b_kk0] = pb0.y;
            Bs[0][(b_dq * 4 + 2) * TN + b_kk0] = pb0.z;
            Bs[0][(b_dq * 4 + 3) * TN + b_kk0] = pb0.w;
            Bs[0][(b_dq * 4 + 0) * TN + b_kk1] = pb1.x;
            Bs[0][(b_dq * 4 + 1) * TN + b_kk1] = pb1.y;
            Bs[0][(b_dq * 4 + 2) * TN + b_kk1] = pb1.z;
            Bs[0][(b_dq * 4 + 3) * TN + b_kk1] = pb1.w;
        }
        __syncthreads();

        for (int it = 0; it < NITER; it++) {
            int cur = it & 1;
            // Prefetch ONLY A into named registers across the compute block
            // (B reloads happen in the short store window below to keep
            //  register pressure under the 128-reg cap).
            float4 pa0, pa1;
            if (it + 1 < NITER) {
                int d0 = (it + 1) * TK;
                pa0 = *(const float4*)(&g_res[(d0 + a_dd0) * NN + n0 + a_nn4 * 4]);
                pa1 = *(const float4*)(&g_res[(d0 + a_dd1) * NN + n0 + a_nn4 * 4]);
            }
            const float* Ash = As[cur];
            const float* Bsh = Bs[cur];
            // FFMA2 microtile: 8 rows x 4 column-pairs, d ascending
#pragma unroll
            for (int d = 0; d < TK; d++) {
                u64 aa[8];
#pragma unroll
                for (int s = 0; s < 4; s++) {
                    ulonglong2 av = *(const ulonglong2*)(&Ash[d * AROW + ty * 16 + s * 4]);
                    aa[2 * s]     = av.x;   // {a_{2s},   a_{2s}}
                    aa[2 * s + 1] = av.y;   // {a_{2s+1}, a_{2s+1}}
                }
                ulonglong2 bb0 = *(const ulonglong2*)(&Bsh[d * TN + tx * 4]);
                ulonglong2 bb1 = *(const ulonglong2*)(&Bsh[d * TN + 64 + tx * 4]);
#pragma unroll
                for (int i = 0; i < 8; i++) {
                    acc[i][0] = ffma2(aa[i], bb0.x, acc[i][0]);
                    acc[i][1] = ffma2(aa[i], bb0.y, acc[i][1]);
                    acc[i][2] = ffma2(aa[i], bb1.x, acc[i][2]);
                    acc[i][3] = ffma2(aa[i], bb1.y, acc[i][3]);
                }
            }
            if (it + 1 < NITER) {
                int d0 = (it + 1) * TK;
                int nxt = 1 - cur;
                // B loads issued here (L2-resident codebook, ~250cyc) overlap
                // the preceding FMA tail + store phase via the scoreboard.
                float4 pb0 = *(const float4*)(&cbq[(size_t)(k0 + b_kk0) * DD + d0 + b_dq * 4]);
                float4 pb1 = *(const float4*)(&cbq[(size_t)(k0 + b_kk1) * DD + d0 + b_dq * 4]);
                float4* da0 = (float4*)(&As[nxt][a_dd0 * AROW + a_nn4 * 8]);
                da0[0] = make_float4(pa0.x, pa0.x, pa0.y, pa0.y);
                da0[1] = make_float4(pa0.z, pa0.z, pa0.w, pa0.w);
                float4* da1 = (float4*)(&As[nxt][a_dd1 * AROW + a_nn4 * 8]);
                da1[0] = make_float4(pa1.x, pa1.x, pa1.y, pa1.y);
                da1[1] = make_float4(pa1.z, pa1.z, pa1.w, pa1.w);
                Bs[nxt][(b_dq * 4 + 0) * TN + b_kk0] = pb0.x;
                Bs[nxt][(b_dq * 4 + 1) * TN + b_kk0] = pb0.y;
                Bs[nxt][(b_dq * 4 + 2) * TN + b_kk0] = pb0.z;
                Bs[nxt][(b_dq * 4 + 3) * TN + b_kk0] = pb0.w;
                Bs[nxt][(b_dq * 4 + 0) * TN + b_kk1] = pb1.x;
                Bs[nxt][(b_dq * 4 + 1) * TN + b_kk1] = pb1.y;
                Bs[nxt][(b_dq * 4 + 2) * TN + b_kk1] = pb1.z;
                Bs[nxt][(b_dq * 4 + 3) * TN + b_kk1] = pb1.w;
                __syncthreads();
            }
        }

        // Epilogue: exact fp32 dist chain + running argmin, k ascending.
        // Thread's column for pair p, lane l:
        //   p=0,1: k0 + tx*4 + 2p + l;  p=2,3: k0 + 64 + tx*4 + 2(p-2) + l
        const float* c2p = &g_c2[q * KK];
#pragma unroll
        for (int i = 0; i < 8; i++) {
            float x2v = __ldg(&g_x2[n0 + ty * 8 + i]);
#pragma unroll
            for (int p = 0; p < 4; p++) {
                int kcol = (p < 2) ? (k0 + tx * 4 + 2 * p)
                                   : (k0 + 64 + tx * 4 + 2 * (p - 2));
                float lo, hi;
                unpack2(acc[i][p], lo, hi);
                float c2lo = __ldg(&c2p[kcol]);
                float c2hi = __ldg(&c2p[kcol + 1]);
                float t0 = __fsub_rn(x2v, 2.0f * lo);   // 2*dot exact
                float d0v = __fadd_rn(t0, c2lo);
                if (d0v < bd[i] || (d0v == bd[i] && kcol < bk[i])) {
                    bd[i] = d0v; bk[i] = kcol;
                }
                float t1 = __fsub_rn(x2v, 2.0f * hi);
                float d1v = __fadd_rn(t1, c2hi);
                if (d1v < bd[i] || (d1v == bd[i] && (kcol + 1) < bk[i])) {
                    bd[i] = d1v; bk[i] = kcol + 1;
                }
            }
        }
        __syncthreads();  // protect buffers before next kt's initial fill
    }

    // cross-thread reduce per row (exact lowest-index tie-break)
    float* sd = As[0];                 // 128*16 floats = 8KB, fits
    int*   sk = (int*)Bs[0];
#pragma unroll
    for (int i = 0; i < 8; i++) {
        sd[(ty * 8 + i) * 16 + tx] = bd[i];
        sk[(ty * 8 + i) * 16 + tx] = bk[i];
    }
    __syncthreads();
    if (tid < TM) {
        float best = sd[tid * 16];
        int kbest = sk[tid * 16];
        for (int j = 1; j < 16; j++) {
            float d2 = sd[tid * 16 + j];
            int   k2 = sk[tid * 16 + j];
            if (d2 < best || (d2 == best && k2 < kbest)) { best = d2; kbest = k2; }
        }
        g_bd2[half * NN + n0 + tid] = best;
        g_bk2[half * NN + n0 + tid] = kbest;
    }
}

// ---------------------------------------------------------------------------
// Merge halves (half 0 = lower indices wins ties) + residual/quantized update
// + loss + next-stage x2 (all reference-faithful fp32).
// q_out = fl(r + fl(quant - r));  qo += q_out;  r = fl(r - q_out)
// ---------------------------------------------------------------------------
__global__ void k_update(const float* __restrict__ cbq, int q,
                         float* __restrict__ idx_out) {
    int n = blockIdx.x * blockDim.x + threadIdx.x;
    double ls = 0.0;
    if (n < NN) {
        float d0 = g_bd2[n], d1 = g_bd2[NN + n];
        int   k0 = g_bk2[n], k1 = g_bk2[NN + n];
        int kbest = (d1 < d0) ? k1 : k0;   // tie -> half 0 (lower index)
        if (idx_out) {
            int b = n / TT, t = n % TT;
            idx_out[(size_t)b * (NQ * TT) + q * TT + t] = (float)kbest;
        }
        const float* crow = cbq + (size_t)kbest * DD;
        float s = 0.0f;
        for (int d = 0; d < DD; d++) {
            int i = d * NN + n;
            float r = g_res[i];
            float c = __ldg(&crow[d]);
            float diff = __fsub_rn(c, r);      // quant - residual
            float qo = __fadd_rn(r, diff);     // q_out
            g_qo[i] = __fadd_rn(g_qo[i], qo);
            float rn = __fsub_rn(r, qo);       // new residual
            g_res[i] = rn;
            ls += (double)__fmul_rn(diff, diff);
            s = __fadd_rn(s, __fmul_rn(rn, rn));  // next-stage x2, same order
        }
        g_x2[n] = s;
    }
    __shared__ double red[256];
    red[threadIdx.x] = ls;
    __syncthreads();
    for (int o = 128; o > 0; o >>= 1) {
        if (threadIdx.x < o) red[threadIdx.x] += red[threadIdx.x + o];
        __syncthreads();
    }
    if (threadIdx.x == 0) atomicAdd(&g_loss[q], red[0]);
}

// ---------------------------------------------------------------------------
// Output: quantized_out [d][n] -> [b][d][t]
// ---------------------------------------------------------------------------
__global__ void k_out_q(float* __restrict__ out) {
    int i = blockIdx.x * blockDim.x + threadIdx.x;
    if (i >= QELEMS) return;
    int b = i / (DD * TT);
    int rem = i % (DD * TT);
    int d = rem / TT;
    int t = rem % TT;
    out[i] = g_qo[d * NN + b * TT + t];
}

__global__ void k_out_loss(float* __restrict__ out) {
    if (threadIdx.x == 0 && blockIdx.x == 0) {
        float tot = 0.0f;
        for (int q = 0; q < NQ; q++) {
            float lq = (float)(g_loss[q] / (double)QELEMS);
            tot = __fadd_rn(tot, lq);
        }
        *out = tot;
    }
}

// ---------------------------------------------------------------------------
extern "C" void kernel_launch(void* const* d_in, const int* in_sizes, int n_in,
                              void* d_out, int out_size) {
    const float* x = (const float*)d_in[0];
    const float* cbs = (const float*)d_in[1];
    // defensive input-order check
    if (n_in >= 2 && in_sizes[0] == NQ * KK * DD && in_sizes[1] == QELEMS) {
        const float* tmp = x; x = cbs; cbs = tmp;
    }
    float* out = (float*)d_out;
    bool full = (out_size >= QELEMS + NQ * TT * BN + 1);

    k_init<<<(QELEMS + 255) / 256, 256>>>(x);
    k_c2<<<(NQ * KK + 255) / 256, 256>>>(cbs);
    k_x2<<<(NN + 255) / 256, 256>>>();

    dim3 ag(NTILE, 2);
    for (int q = 0; q < NQ; q++) {
        const float* cbq = cbs + (size_t)q * KK * DD;
        k_argmin<<<ag, 256>>>(cbq, q);
        k_update<<<(NN + 255) / 256, 256>>>(cbq, q, full ? out + QELEMS : nullptr);
    }

    k_out_q<<<(QELEMS + 255) / 256, 256>>>(out);
    if (full) k_out_loss<<<1, 32>>>(out + QELEMS + (size_t)NQ * TT * BN);
}

// round 11
// speedup vs baseline: 1.1676x; 1.1676x over previous
#include <cuda_runtime.h>
#include <math_constants.h>

// Problem constants
#define BN 32
#define TT 1500
#define DD 512
#define KK 2048
#define NQ 8
#define NN (BN * TT)          // 48000 vectors
#define QELEMS (BN * DD * TT) // 24576000 elements of quantized output

// GEMM tiling
#define TM 128
#define TN 128
#define TK 16
#define NITER (DD / TK)       // 32 d-steps per column tile
#define KHALF (KK / 2)        // 1024 codes per half
#define NTILE (NN / TM)       // 375 row tiles

// k_update staging
#define UB 128                // n's per update block
#define UCH 64                // d-chunk staged in smem

typedef unsigned long long u64;

// Packed fp32x2 FMA: two IEEE .rn fp32 FMAs per instruction (bit-identical to
// scalar fmaf per lane; ptxas never emits it from C++).
__device__ __forceinline__ u64 ffma2(u64 a, u64 b, u64 c) {
    u64 d;
    asm("fma.rn.f32x2 %0, %1, %2, %3;" : "=l"(d) : "l"(a), "l"(b), "l"(c));
    return d;
}
__device__ __forceinline__ void unpack2(u64 v, float& lo, float& hi) {
    asm("mov.b64 {%0, %1}, %2;" : "=f"(lo), "=f"(hi) : "l"(v));
}
// Build {a, a} register pair from one float (replaces smem-side duplication).
// b32 "r" constraint form matches the proven PACK_F32X2 macro style.
__device__ __forceinline__ u64 pack_dup(float a) {
    unsigned int u = __float_as_uint(a);
    u64 d;
    asm("mov.b64 %0, {%1, %1};" : "=l"(d) : "r"(u));
    return d;
}

// Scratch (allocation-free rule: __device__ globals)
__device__ __align__(16) float  g_res[QELEMS];   // residual, layout [d][n]  (n = b*TT + t)
__device__ __align__(16) float  g_qo[QELEMS];    // accumulated quantized_out, layout [d][n]
__device__ __align__(16) float  g_x2[NN];        // ||residual_n||^2
__device__ __align__(16) float  g_c2[NQ * KK];   // ||cb_{q,k}||^2
__device__ __align__(16) float  g_bd2[2 * NN];   // per-half best distance
__device__ int    g_bk2[2 * NN];                 // per-half best index
__device__ double g_loss[NQ];                    // per-stage sum of (quant - residual)^2

// ---------------------------------------------------------------------------
// init: transpose x [B,D,T] -> g_res [d][n], zero g_qo and g_loss
// ---------------------------------------------------------------------------
__global__ void k_init(const float* __restrict__ x) {
    int i = blockIdx.x * blockDim.x + threadIdx.x;
    if (i >= QELEMS) return;
    int n = i % NN;
    int d = i / NN;
    int b = n / TT;
    int t = n % TT;
    g_res[i] = x[(size_t)b * (DD * TT) + (size_t)d * TT + t];
    g_qo[i] = 0.0f;
    if (i < NQ) g_loss[i] = 0.0;
}

// ---------------------------------------------------------------------------
// c2[q*KK + k] = sum_d cb[q,k,d]^2   (fp32 mul-then-add, sequential d)
// ---------------------------------------------------------------------------
__global__ void k_c2(const float* __restrict__ cbs) {
    int i = blockIdx.x * blockDim.x + threadIdx.x;
    if (i >= NQ * KK) return;
    const float* row = cbs + (size_t)i * DD;
    float s = 0.0f;
    for (int d = 0; d < DD; d++) {
        float v = __ldg(&row[d]);
        s = __fadd_rn(s, __fmul_rn(v, v));
    }
    g_c2[i] = s;
}

// ---------------------------------------------------------------------------
// x2[n] = sum_d res[d][n]^2  (stage 0; later stages fused into k_update)
// ---------------------------------------------------------------------------
__global__ void k_x2() {
    int n = blockIdx.x * blockDim.x + threadIdx.x;
    if (n >= NN) return;
    float s = 0.0f;
    for (int d = 0; d < DD; d++) {
        float v = g_res[d * NN + n];
        s = __fadd_rn(s, __fmul_rn(v, v));
    }
    g_x2[n] = s;
}

// ---------------------------------------------------------------------------
// Distance GEMM + argmin over one half of the codebook, FFMA2 inner loop.
// blockIdx.x = row tile (0..374), blockIdx.y = code half (0/1).
// A tile stored NATURALLY (no duplication); the packed {a,a} operand is built
// in registers via mov.b64 {r,r} (alu pipe has headroom, L1 was the binding
// pipe at 79.4%). B pairs are naturally contiguous.
// dist = fl(fl(x2 - 2*dot) + c2); exact lowest-index tie-break everywhere.
// ---------------------------------------------------------------------------
__global__ __launch_bounds__(256, 2)
void k_argmin(const float* __restrict__ cbq, int q) {
    __shared__ __align__(16) float As[2][TK * TM];    // 2 x 8KB (natural)
    __shared__ __align__(16) float Bs[2][TK * TN];    // 2 x 8KB

    int tid = threadIdx.x;
    int tx = tid & 15;
    int ty = tid >> 4;
    int n0 = blockIdx.x * TM;
    int half = blockIdx.y;
    int kbase = half * KHALF;

    // per-thread load slots (2 float4 for A, 2 for B)
    const int a_dd0  = tid >> 5;            // 0..7
    const int a_dd1  = (tid + 256) >> 5;    // 8..15
    const int a_nn4  = tid & 31;            // float4 slot along n
    const int b_kk0  = tid >> 2;            // 0..63
    const int b_kk1  = (tid + 256) >> 2;    // 64..127
    const int b_dq   = tid & 3;             // float4 slot along d

    float bd[8];
    int   bk[8];
#pragma unroll
    for (int i = 0; i < 8; i++) { bd[i] = CUDART_INF_F; bk[i] = 0x7fffffff; }

    for (int kt = 0; kt < KHALF / TN; kt++) {
        int k0 = kbase + kt * TN;
        u64 acc[8][4];
#pragma unroll
        for (int i = 0; i < 8; i++)
#pragma unroll
            for (int p = 0; p < 4; p++) acc[i][p] = 0ull;

        // ---- fill buffer 0 (d0 = 0) ----
        {
            float4 pa0 = *(const float4*)(&g_res[a_dd0 * NN + n0 + a_nn4 * 4]);
            float4 pa1 = *(const float4*)(&g_res[a_dd1 * NN + n0 + a_nn4 * 4]);
            float4 pb0 = *(const float4*)(&cbq[(size_t)(k0 + b_kk0) * DD + b_dq * 4]);
            float4 pb1 = *(const float4*)(&cbq[(size_t)(k0 + b_kk1) * DD + b_dq * 4]);
            *(float4*)(&As[0][a_dd0 * TM + a_nn4 * 4]) = pa0;
            *(float4*)(&As[0][a_dd1 * TM + a_nn4 * 4]) = pa1;
            Bs[0][(b_dq * 4 + 0) * TN + b_kk0] = pb0.x;
            Bs[0][(b_dq * 4 + 1) * TN + b_kk0] = pb0.y;
            Bs[0][(b_dq * 4 + 2) * TN + b_kk0] = pb0.z;
            Bs[0][(b_dq * 4 + 3) * TN + b_kk0] = pb0.w;
            Bs[0][(b_dq * 4 + 0) * TN + b_kk1] = pb1.x;
            Bs[0][(b_dq * 4 + 1) * TN + b_kk1] = pb1.y;
            Bs[0][(b_dq * 4 + 2) * TN + b_kk1] = pb1.z;
            Bs[0][(b_dq * 4 + 3) * TN + b_kk1] = pb1.w;
        }
        __syncthreads();

        for (int it = 0; it < NITER; it++) {
            int cur = it & 1;
            // Prefetch ONLY A into named registers across the compute block
            // (B reloads happen in the short store window below to keep
            //  register pressure under the 128-reg cap).
            float4 pa0, pa1;
            if (it + 1 < NITER) {
                int d0 = (it + 1) * TK;
                pa0 = *(const float4*)(&g_res[(d0 + a_dd0) * NN + n0 + a_nn4 * 4]);
                pa1 = *(const float4*)(&g_res[(d0 + a_dd1) * NN + n0 + a_nn4 * 4]);
            }
            const float* Ash = As[cur];
            const float* Bsh = Bs[cur];
            // FFMA2 microtile: 8 rows x 4 column-pairs, d ascending
#pragma unroll
            for (int d = 0; d < TK; d++) {
                float a8[8];
                *(float4*)&a8[0] = *(const float4*)&Ash[d * TM + ty * 8];
                *(float4*)&a8[4] = *(const float4*)&Ash[d * TM + ty * 8 + 4];
                u64 aa[8];
#pragma unroll
                for (int i = 0; i < 8; i++) aa[i] = pack_dup(a8[i]);
                ulonglong2 bb0 = *(const ulonglong2*)(&Bsh[d * TN + tx * 4]);
                ulonglong2 bb1 = *(const ulonglong2*)(&Bsh[d * TN + 64 + tx * 4]);
#pragma unroll
                for (int i = 0; i < 8; i++) {
                    acc[i][0] = ffma2(aa[i], bb0.x, acc[i][0]);
                    acc[i][1] = ffma2(aa[i], bb0.y, acc[i][1]);
                    acc[i][2] = ffma2(aa[i], bb1.x, acc[i][2]);
                    acc[i][3] = ffma2(aa[i], bb1.y, acc[i][3]);
                }
            }
            if (it + 1 < NITER) {
                int d0 = (it + 1) * TK;
                int nxt = 1 - cur;
                // B loads issued here (L2-resident codebook) overlap the FMA
                // tail + store phase via the scoreboard.
                float4 pb0 = *(const float4*)(&cbq[(size_t)(k0 + b_kk0) * DD + d0 + b_dq * 4]);
                float4 pb1 = *(const float4*)(&cbq[(size_t)(k0 + b_kk1) * DD + d0 + b_dq * 4]);
                *(float4*)(&As[nxt][a_dd0 * TM + a_nn4 * 4]) = pa0;
                *(float4*)(&As[nxt][a_dd1 * TM + a_nn4 * 4]) = pa1;
                Bs[nxt][(b_dq * 4 + 0) * TN + b_kk0] = pb0.x;
                Bs[nxt][(b_dq * 4 + 1) * TN + b_kk0] = pb0.y;
                Bs[nxt][(b_dq * 4 + 2) * TN + b_kk0] = pb0.z;
                Bs[nxt][(b_dq * 4 + 3) * TN + b_kk0] = pb0.w;
                Bs[nxt][(b_dq * 4 + 0) * TN + b_kk1] = pb1.x;
                Bs[nxt][(b_dq * 4 + 1) * TN + b_kk1] = pb1.y;
                Bs[nxt][(b_dq * 4 + 2) * TN + b_kk1] = pb1.z;
                Bs[nxt][(b_dq * 4 + 3) * TN + b_kk1] = pb1.w;
                __syncthreads();
            }
        }

        // Epilogue: exact fp32 dist chain + running argmin, k ascending.
        // Thread's column for pair p, lane l:
        //   p=0,1: k0 + tx*4 + 2p + l;  p=2,3: k0 + 64 + tx*4 + 2(p-2) + l
        const float* c2p = &g_c2[q * KK];
#pragma unroll
        for (int i = 0; i < 8; i++) {
            float x2v = __ldg(&g_x2[n0 + ty * 8 + i]);
#pragma unroll
            for (int p = 0; p < 4; p++) {
                int kcol = (p < 2) ? (k0 + tx * 4 + 2 * p)
                                   : (k0 + 64 + tx * 4 + 2 * (p - 2));
                float lo, hi;
                unpack2(acc[i][p], lo, hi);
                float c2lo = __ldg(&c2p[kcol]);
                float c2hi = __ldg(&c2p[kcol + 1]);
                float t0 = __fsub_rn(x2v, 2.0f * lo);   // 2*dot exact
                float d0v = __fadd_rn(t0, c2lo);
                if (d0v < bd[i] || (d0v == bd[i] && kcol < bk[i])) {
                    bd[i] = d0v; bk[i] = kcol;
                }
                float t1 = __fsub_rn(x2v, 2.0f * hi);
                float d1v = __fadd_rn(t1, c2hi);
                if (d1v < bd[i] || (d1v == bd[i] && (kcol + 1) < bk[i])) {
                    bd[i] = d1v; bk[i] = kcol + 1;
                }
            }
        }
        __syncthreads();  // protect buffers before next kt's initial fill
    }

    // cross-thread reduce per row (exact lowest-index tie-break)
    float* sd = As[0];                 // 128*16 floats = 8KB, fits
    int*   sk = (int*)Bs[0];
#pragma unroll
    for (int i = 0; i < 8; i++) {
        sd[(ty * 8 + i) * 16 + tx] = bd[i];
        sk[(ty * 8 + i) * 16 + tx] = bk[i];
    }
    __syncthreads();
    if (tid < TM) {
        float best = sd[tid * 16];
        int kbest = sk[tid * 16];
        for (int j = 1; j < 16; j++) {
            float d2 = sd[tid * 16 + j];
            int   k2 = sk[tid * 16 + j];
            if (d2 < best || (d2 == best && k2 < kbest)) { best = d2; kbest = k2; }
        }
        g_bd2[half * NN + n0 + tid] = best;
        g_bk2[half * NN + n0 + tid] = kbest;
    }
}

// ---------------------------------------------------------------------------
// Merge halves (half 0 wins ties) + residual/quantized update + loss +
// next-stage x2. Codebook rows are staged through smem in 64-d chunks
// (cooperative coalesced loads) to kill the 32-distinct-rows/warp sector
// amplification of the old per-thread gather. Exact fp32 chain and d-ascending
// accumulation order preserved bit-for-bit.
// ---------------------------------------------------------------------------
__global__ __launch_bounds__(UB)
void k_update(const float* __restrict__ cbq, int q, float* __restrict__ idx_out) {
    __shared__ float  rows[UB][UCH + 1];   // stride 65: conflict-free column reads
    __shared__ int    kbs[UB];
    __shared__ double red[UB];

    int t = threadIdx.x;
    int n0 = blockIdx.x * UB;
    int n = n0 + t;

    // merge + index output
    {
        float d0 = g_bd2[n], d1 = g_bd2[NN + n];
        int   k0 = g_bk2[n], k1 = g_bk2[NN + n];
        int kbest = (d1 < d0) ? k1 : k0;   // tie -> half 0 (lower index)
        kbs[t] = kbest;
        if (idx_out) {
            int b = n / TT, tt = n % TT;
            idx_out[(size_t)b * (NQ * TT) + q * TT + tt] = (float)kbest;
        }
    }
    __syncthreads();

    int w = t >> 5, l = t & 31;
    double ls = 0.0;
    float s = 0.0f;

    for (int dc = 0; dc < DD; dc += UCH) {
        // cooperative staged load: warp w handles rows w, w+4, ... (coalesced)
        for (int r = w; r < UB; r += 4) {
            const float* crow = cbq + (size_t)kbs[r] * DD + dc;
            rows[r][l]      = __ldg(&crow[l]);
            rows[r][l + 32] = __ldg(&crow[l + 32]);
        }
        __syncthreads();

        for (int dd = 0; dd < UCH; dd++) {
            int d = dc + dd;
            int i = d * NN + n;
            float r = g_res[i];
            float c = rows[t][dd];
            float diff = __fsub_rn(c, r);      // quant - residual
            float qo = __fadd_rn(r, diff);     // q_out
            g_qo[i] = __fadd_rn(g_qo[i], qo);
            float rn = __fsub_rn(r, qo);       // new residual
            g_res[i] = rn;
            ls += (double)__fmul_rn(diff, diff);
            s = __fadd_rn(s, __fmul_rn(rn, rn));  // next-stage x2, same order
        }
        __syncthreads();
    }
    g_x2[n] = s;

    red[t] = ls;
    __syncthreads();
    for (int o = UB / 2; o > 0; o >>= 1) {
        if (t < o) red[t] += red[t + o];
        __syncthreads();
    }
    if (t == 0) atomicAdd(&g_loss[q], red[0]);
}

// ---------------------------------------------------------------------------
// Output: quantized_out [d][n] -> [b][d][t]
// ---------------------------------------------------------------------------
__global__ void k_out_q(float* __restrict__ out) {
    int i = blockIdx.x * blockDim.x + threadIdx.x;
    if (i >= QELEMS) return;
    int b = i / (DD * TT);
    int rem = i % (DD * TT);
    int d = rem / TT;
    int t = rem % TT;
    out[i] = g_qo[d * NN + b * TT + t];
}

__global__ void k_out_loss(float* __restrict__ out) {
    if (threadIdx.x == 0 && blockIdx.x == 0) {
        float tot = 0.0f;
        for (int q = 0; q < NQ; q++) {
            float lq = (float)(g_loss[q] / (double)QELEMS);
            tot = __fadd_rn(tot, lq);
        }
        *out = tot;
    }
}

// ---------------------------------------------------------------------------
extern "C" void kernel_launch(void* const* d_in, const int* in_sizes, int n_in,
                              void* d_out, int out_size) {
    const float* x = (const float*)d_in[0];
    const float* cbs = (const float*)d_in[1];
    // defensive input-order check
    if (n_in >= 2 && in_sizes[0] == NQ * KK * DD && in_sizes[1] == QELEMS) {
        const float* tmp = x; x = cbs; cbs = tmp;
    }
    float* out = (float*)d_out;
    bool full = (out_size >= QELEMS + NQ * TT * BN + 1);

    k_init<<<(QELEMS + 255) / 256, 256>>>(x);
    k_c2<<<(NQ * KK + 255) / 256, 256>>>(cbs);
    k_x2<<<(NN + 255) / 256, 256>>>();

    dim3 ag(NTILE, 2);
    for (int q = 0; q < NQ; q++) {
        const float* cbq = cbs + (size_t)q * KK * DD;
        k_argmin<<<ag, 256>>>(cbq, q);
        k_update<<<NN / UB, UB>>>(cbq, q, full ? out + QELEMS : nullptr);
    }

    k_out_q<<<(QELEMS + 255) / 256, 256>>>(out);
    if (full) k_out_loss<<<1, 32>>>(out + QELEMS + (size_t)NQ * TT * BN);
}